// round 1
// baseline (speedup 1.0000x reference)
#include <cuda_runtime.h>

#define NDIM 8192
#define ROWS_PER_BLOCK 8
#define THREADS 256
#define NBLOCKS (NDIM / ROWS_PER_BLOCK)   // 1024
#define VEC_PER_ROW (NDIM / 4)            // 2048 float4 per row
#define K_ITERS (VEC_PER_ROW / THREADS)   // 8 float4 per thread per row

// Scratch for deterministic two-stage reduction (no cudaMalloc allowed).
__device__ float g_partA[NBLOCKS];   // per-block sum of all matrix elements
__device__ float g_partB[NBLOCKS];   // per-block sum of s_i * (sum_{j>i} M_ij s_j + M_ii)

__global__ __launch_bounds__(THREADS)
void ising_pass1(const float* __restrict__ M, const float* __restrict__ s) {
    __shared__ float s_sh[NDIM];            // 32 KB
    __shared__ float redA[THREADS];
    __shared__ float redB[THREADS];

    const int tid = threadIdx.x;

    // Stage state vector into shared (vectorized, coalesced).
    {
        const float4* s4 = reinterpret_cast<const float4*>(s);
        float4* sh4 = reinterpret_cast<float4*>(s_sh);
        #pragma unroll
        for (int k = tid; k < NDIM / 4; k += THREADS) {
            sh4[k] = s4[k];
        }
    }
    __syncthreads();

    const float4* sh4 = reinterpret_cast<const float4*>(s_sh);
    const int row0 = blockIdx.x * ROWS_PER_BLOCK;

    float aAcc = 0.0f;   // plain sum
    float bAcc = 0.0f;   // weighted sum

    #pragma unroll
    for (int r = 0; r < ROWS_PER_BLOCK; ++r) {
        const int i = row0 + r;
        const float si = s_sh[i];
        const float4* row = reinterpret_cast<const float4*>(M + (size_t)i * NDIM);

        float rowsum = 0.0f;
        float rowdot = 0.0f;

        #pragma unroll
        for (int k = 0; k < K_ITERS; ++k) {
            const int j4 = tid + k * THREADS;
            const float4 v  = row[j4];       // LDG.128, coalesced
            const float4 sv = sh4[j4];       // LDS.128, conflict-free
            const int j = j4 * 4;

            rowsum += (v.x + v.y) + (v.z + v.w);

            float w0 = (j + 0 > i) ? sv.x : ((j + 0 == i) ? 1.0f : 0.0f);
            float w1 = (j + 1 > i) ? sv.y : ((j + 1 == i) ? 1.0f : 0.0f);
            float w2 = (j + 2 > i) ? sv.z : ((j + 2 == i) ? 1.0f : 0.0f);
            float w3 = (j + 3 > i) ? sv.w : ((j + 3 == i) ? 1.0f : 0.0f);

            rowdot = fmaf(v.x, w0, rowdot);
            rowdot = fmaf(v.y, w1, rowdot);
            rowdot = fmaf(v.z, w2, rowdot);
            rowdot = fmaf(v.w, w3, rowdot);
        }

        aAcc += rowsum;
        bAcc = fmaf(si, rowdot, bAcc);
    }

    // Block tree reduction (deterministic).
    redA[tid] = aAcc;
    redB[tid] = bAcc;
    __syncthreads();
    #pragma unroll
    for (int st = THREADS / 2; st > 0; st >>= 1) {
        if (tid < st) {
            redA[tid] += redA[tid + st];
            redB[tid] += redB[tid + st];
        }
        __syncthreads();
    }

    if (tid == 0) {
        g_partA[blockIdx.x] = redA[0];
        g_partB[blockIdx.x] = redB[0];
    }
}

__global__ __launch_bounds__(THREADS)
void ising_pass2(float* __restrict__ out) {
    __shared__ double rA[THREADS];
    __shared__ double rB[THREADS];

    const int tid = threadIdx.x;
    double a = 0.0, b = 0.0;
    for (int k = tid; k < NBLOCKS; k += THREADS) {
        a += (double)g_partA[k];
        b += (double)g_partB[k];
    }
    rA[tid] = a;
    rB[tid] = b;
    __syncthreads();
    #pragma unroll
    for (int st = THREADS / 2; st > 0; st >>= 1) {
        if (tid < st) {
            rA[tid] += rA[tid + st];
            rB[tid] += rB[tid + st];
        }
        __syncthreads();
    }

    if (tid == 0) {
        // out = sum(M)/4 - 0.5 * (sum_{i<j} M_ij s_i s_j + sum_i M_ii s_i)
        double res = rA[0] * 0.25 - 0.5 * rB[0];
        out[0] = (float)res;
    }
}

extern "C" void kernel_launch(void* const* d_in, const int* in_sizes, int n_in,
                              void* d_out, int out_size) {
    const float* M = (const float*)d_in[0];   // info_mtx [8192, 8192] fp32
    const float* s = (const float*)d_in[1];   // state [8192] fp32
    float* out = (float*)d_out;

    ising_pass1<<<NBLOCKS, THREADS>>>(M, s);
    ising_pass2<<<1, THREADS>>>(out);
}

// round 2
// speedup vs baseline: 2.2322x; 2.2322x over previous
#include <cuda_runtime.h>

#define NDIM 8192
#define THREADS 256
#define WARPS_PER_BLOCK 8
#define NBLOCKS (NDIM / WARPS_PER_BLOCK)   // 1024 blocks, one row per warp
#define CHUNKS 64                          // 64 chunks of 32 float4 per row (2048 vecs)

// Scratch for deterministic two-stage reduction (no cudaMalloc allowed).
__device__ float g_partA[NBLOCKS];   // per-block sum of matrix elements
__device__ float g_partB[NBLOCKS];   // per-block sum of s_i * (sum_{j>i} M_ij s_j + M_ii)

__global__ __launch_bounds__(THREADS)
void ising_pass1(const float* __restrict__ M, const float* __restrict__ s) {
    __shared__ float s_sh[NDIM];       // 32 KB
    __shared__ float redA[THREADS];
    __shared__ float redB[THREADS];

    const int tid  = threadIdx.x;
    const int lane = tid & 31;
    const int wid  = tid >> 5;

    // Stage state vector into shared (vectorized, coalesced).
    {
        const float4* s4g = reinterpret_cast<const float4*>(s);
        float4* sh4w = reinterpret_cast<float4*>(s_sh);
        for (int k = tid; k < NDIM / 4; k += THREADS) sh4w[k] = s4g[k];
    }
    __syncthreads();

    const float4* sh4 = reinterpret_cast<const float4*>(s_sh);

    const int i = blockIdx.x * WARPS_PER_BLOCK + wid;      // this warp's row
    const float4* row = reinterpret_cast<const float4*>(M + (size_t)i * NDIM);
    const int vs = i >> 2;        // float4 index containing the diagonal element
    const int cm = vs >> 5;       // chunk index containing the diagonal (0..63)

    // Split accumulators to break FP dependency chains.
    float a0 = 0.f, a1 = 0.f, a2 = 0.f, a3 = 0.f;   // plain sum
    float d0 = 0.f, d1 = 0.f, d2 = 0.f, d3 = 0.f;   // upper-tri dot

    // ---- Region A: chunks [0, cm) — strictly below diagonal: sum only ----
    int c = 0;
    #pragma unroll 1
    for (; c + 4 <= cm; c += 4) {
        const float4 v0 = row[(c + 0) * 32 + lane];
        const float4 v1 = row[(c + 1) * 32 + lane];
        const float4 v2 = row[(c + 2) * 32 + lane];
        const float4 v3 = row[(c + 3) * 32 + lane];
        a0 += v0.x + v0.y;  a1 += v0.z + v0.w;
        a2 += v1.x + v1.y;  a3 += v1.z + v1.w;
        a0 += v2.x + v2.y;  a1 += v2.z + v2.w;
        a2 += v3.x + v3.y;  a3 += v3.z + v3.w;
    }
    #pragma unroll 1
    for (; c < cm; ++c) {
        const float4 v = row[c * 32 + lane];
        a0 += v.x + v.y;  a1 += v.z + v.w;
    }

    // ---- Mixed chunk c == cm: element-wise selects (only 32 vecs per row) ----
    {
        const int j4 = cm * 32 + lane;
        const float4 v  = row[j4];
        const float4 sv = sh4[j4];
        const int j = j4 * 4;
        a0 += v.x + v.y;  a1 += v.z + v.w;
        const float w0 = (j + 0 > i) ? sv.x : ((j + 0 == i) ? 1.0f : 0.0f);
        const float w1 = (j + 1 > i) ? sv.y : ((j + 1 == i) ? 1.0f : 0.0f);
        const float w2 = (j + 2 > i) ? sv.z : ((j + 2 == i) ? 1.0f : 0.0f);
        const float w3 = (j + 3 > i) ? sv.w : ((j + 3 == i) ? 1.0f : 0.0f);
        d0 = fmaf(v.x, w0, d0);
        d1 = fmaf(v.y, w1, d1);
        d2 = fmaf(v.z, w2, d2);
        d3 = fmaf(v.w, w3, d3);
    }

    // ---- Region B: chunks (cm, 64) — strictly above diagonal: sum + dot ----
    c = cm + 1;
    #pragma unroll 1
    for (; c + 4 <= CHUNKS; c += 4) {
        const int b = c * 32 + lane;
        const float4 v0 = row[b + 0 * 32];
        const float4 v1 = row[b + 1 * 32];
        const float4 v2 = row[b + 2 * 32];
        const float4 v3 = row[b + 3 * 32];
        const float4 t0 = sh4[b + 0 * 32];
        const float4 t1 = sh4[b + 1 * 32];
        const float4 t2 = sh4[b + 2 * 32];
        const float4 t3 = sh4[b + 3 * 32];
        a0 += v0.x + v0.y;  a1 += v0.z + v0.w;
        a2 += v1.x + v1.y;  a3 += v1.z + v1.w;
        a0 += v2.x + v2.y;  a1 += v2.z + v2.w;
        a2 += v3.x + v3.y;  a3 += v3.z + v3.w;
        d0 = fmaf(v0.x, t0.x, d0);  d1 = fmaf(v0.y, t0.y, d1);
        d2 = fmaf(v0.z, t0.z, d2);  d3 = fmaf(v0.w, t0.w, d3);
        d0 = fmaf(v1.x, t1.x, d0);  d1 = fmaf(v1.y, t1.y, d1);
        d2 = fmaf(v1.z, t1.z, d2);  d3 = fmaf(v1.w, t1.w, d3);
        d0 = fmaf(v2.x, t2.x, d0);  d1 = fmaf(v2.y, t2.y, d1);
        d2 = fmaf(v2.z, t2.z, d2);  d3 = fmaf(v2.w, t2.w, d3);
        d0 = fmaf(v3.x, t3.x, d0);  d1 = fmaf(v3.y, t3.y, d1);
        d2 = fmaf(v3.z, t3.z, d2);  d3 = fmaf(v3.w, t3.w, d3);
    }
    #pragma unroll 1
    for (; c < CHUNKS; ++c) {
        const int b = c * 32 + lane;
        const float4 v = row[b];
        const float4 t = sh4[b];
        a0 += v.x + v.y;  a1 += v.z + v.w;
        d0 = fmaf(v.x, t.x, d0);  d1 = fmaf(v.y, t.y, d1);
        d2 = fmaf(v.z, t.z, d2);  d3 = fmaf(v.w, t.w, d3);
    }

    // Per-thread totals; multiply dot by s_i (linear, so per-thread is fine).
    const float aAcc = (a0 + a1) + (a2 + a3);
    const float bAcc = s_sh[i] * ((d0 + d1) + (d2 + d3));

    // Deterministic block tree reduction.
    redA[tid] = aAcc;
    redB[tid] = bAcc;
    __syncthreads();
    #pragma unroll
    for (int st = THREADS / 2; st > 0; st >>= 1) {
        if (tid < st) {
            redA[tid] += redA[tid + st];
            redB[tid] += redB[tid + st];
        }
        __syncthreads();
    }
    if (tid == 0) {
        g_partA[blockIdx.x] = redA[0];
        g_partB[blockIdx.x] = redB[0];
    }
}

__global__ __launch_bounds__(THREADS)
void ising_pass2(float* __restrict__ out) {
    __shared__ double rA[THREADS];
    __shared__ double rB[THREADS];

    const int tid = threadIdx.x;
    double a = 0.0, b = 0.0;
    for (int k = tid; k < NBLOCKS; k += THREADS) {
        a += (double)g_partA[k];
        b += (double)g_partB[k];
    }
    rA[tid] = a;
    rB[tid] = b;
    __syncthreads();
    #pragma unroll
    for (int st = THREADS / 2; st > 0; st >>= 1) {
        if (tid < st) {
            rA[tid] += rA[tid + st];
            rB[tid] += rB[tid + st];
        }
        __syncthreads();
    }
    if (tid == 0) {
        // out = sum(M)/4 - 0.5 * (sum_{i<j} M_ij s_i s_j + sum_i M_ii s_i)
        out[0] = (float)(rA[0] * 0.25 - 0.5 * rB[0]);
    }
}

extern "C" void kernel_launch(void* const* d_in, const int* in_sizes, int n_in,
                              void* d_out, int out_size) {
    const float* M = (const float*)d_in[0];   // info_mtx [8192, 8192] fp32
    const float* s = (const float*)d_in[1];   // state [8192] fp32
    float* out = (float*)d_out;

    ising_pass1<<<NBLOCKS, THREADS>>>(M, s);
    ising_pass2<<<1, THREADS>>>(out);
}

// round 3
// speedup vs baseline: 2.6374x; 1.1815x over previous
#include <cuda_runtime.h>

#define NDIM 8192
#define THREADS 256
#define WARPS_PER_BLOCK 8
#define NBLOCKS (NDIM / WARPS_PER_BLOCK)   // 1024 blocks, one row per warp
#define CHUNKS 64                          // 64 chunks of 32 float4 per row

// Scratch for deterministic two-stage reduction (no cudaMalloc allowed).
__device__ float g_partA[NBLOCKS];   // per-block sum of matrix elements
__device__ float g_partB[NBLOCKS];   // per-block sum of s_i * (upper-dot + diag)
__device__ int   g_count = 0;        // completed-block counter (reset by last block)

// Packed f32x2 helpers (sm_103a). Operands are 2 packed fp32 in a 64-bit reg.
__device__ __forceinline__ void fma2(unsigned long long& d,
                                     unsigned long long a,
                                     unsigned long long b) {
    asm("fma.rn.f32x2 %0, %1, %2, %0;" : "+l"(d) : "l"(a), "l"(b));
}
__device__ __forceinline__ void add2(unsigned long long& d,
                                     unsigned long long a) {
    asm("add.rn.f32x2 %0, %0, %1;" : "+l"(d) : "l"(a));
}
__device__ __forceinline__ float lo2(unsigned long long p) {
    unsigned int l, h;
    asm("mov.b64 {%0, %1}, %2;" : "=r"(l), "=r"(h) : "l"(p));
    return __uint_as_float(l);
}
__device__ __forceinline__ float hi2(unsigned long long p) {
    unsigned int l, h;
    asm("mov.b64 {%0, %1}, %2;" : "=r"(l), "=r"(h) : "l"(p));
    return __uint_as_float(h);
}

__global__ __launch_bounds__(THREADS, 6)
void ising_pass1(const float* __restrict__ M, const float* __restrict__ s,
                 float* __restrict__ out) {
    __shared__ float s_sh[NDIM];          // 32 KB
    __shared__ float sA[WARPS_PER_BLOCK];
    __shared__ float sB[WARPS_PER_BLOCK];
    __shared__ int s_isLast;

    const int tid  = threadIdx.x;
    const int lane = tid & 31;
    const int wid  = tid >> 5;

    // Stage state vector into shared (vectorized, coalesced).
    {
        const float4* s4g = reinterpret_cast<const float4*>(s);
        float4* sh4w = reinterpret_cast<float4*>(s_sh);
        for (int k = tid; k < NDIM / 4; k += THREADS) sh4w[k] = s4g[k];
    }
    __syncthreads();

    const int i = blockIdx.x * WARPS_PER_BLOCK + wid;      // this warp's row
    const float* rowf = M + (size_t)i * NDIM;
    const ulonglong2* row64 = reinterpret_cast<const ulonglong2*>(rowf);
    const ulonglong2* sh64  = reinterpret_cast<const ulonglong2*>(s_sh);
    const int cm = i >> 7;        // chunk (of 128 cols) containing the diagonal

    // Packed accumulators: a = plain sum, d = upper-tri dot.
    unsigned long long a01 = 0ull, a23 = 0ull;
    unsigned long long d01 = 0ull, d23 = 0ull;

    // ---- Region A: chunks [0, cm) — strictly below diagonal: sum only ----
    {
        const ulonglong2* rp = row64 + lane;
        int c = 0;
        #pragma unroll 1
        for (; c + 4 <= cm; c += 4) {
            const ulonglong2 v0 = rp[0];
            const ulonglong2 v1 = rp[32];
            const ulonglong2 v2 = rp[64];
            const ulonglong2 v3 = rp[96];
            rp += 128;
            add2(a01, v0.x);  add2(a23, v0.y);
            add2(a01, v1.x);  add2(a23, v1.y);
            add2(a01, v2.x);  add2(a23, v2.y);
            add2(a01, v3.x);  add2(a23, v3.y);
        }
        #pragma unroll 1
        for (; c < cm; ++c) {
            const ulonglong2 v = rp[0];
            rp += 32;
            add2(a01, v.x);  add2(a23, v.y);
        }
    }

    // ---- Mixed chunk c == cm: element-wise selects (32 vecs per row) ----
    float am = 0.0f, dm = 0.0f;
    {
        const int j4 = cm * 32 + lane;
        const float4 v  = reinterpret_cast<const float4*>(rowf)[j4];
        const float4 sv = reinterpret_cast<const float4*>(s_sh)[j4];
        const int j = j4 * 4;
        am = (v.x + v.y) + (v.z + v.w);
        const float w0 = (j + 0 > i) ? sv.x : ((j + 0 == i) ? 1.0f : 0.0f);
        const float w1 = (j + 1 > i) ? sv.y : ((j + 1 == i) ? 1.0f : 0.0f);
        const float w2 = (j + 2 > i) ? sv.z : ((j + 2 == i) ? 1.0f : 0.0f);
        const float w3 = (j + 3 > i) ? sv.w : ((j + 3 == i) ? 1.0f : 0.0f);
        dm = fmaf(v.x, w0, fmaf(v.y, w1, fmaf(v.z, w2, v.w * w3)));
    }

    // ---- Region B: chunks (cm, 64) — strictly above diagonal: sum + dot ----
    {
        int c = cm + 1;
        const ulonglong2* rp = row64 + c * 32 + lane;
        const ulonglong2* sp = sh64  + c * 32 + lane;
        #pragma unroll 1
        for (; c + 2 <= CHUNKS; c += 2) {
            const ulonglong2 v0 = rp[0];
            const ulonglong2 v1 = rp[32];
            const ulonglong2 t0 = sp[0];
            const ulonglong2 t1 = sp[32];
            rp += 64;  sp += 64;
            add2(a01, v0.x);  add2(a23, v0.y);
            fma2(d01, v0.x, t0.x);  fma2(d23, v0.y, t0.y);
            add2(a01, v1.x);  add2(a23, v1.y);
            fma2(d01, v1.x, t1.x);  fma2(d23, v1.y, t1.y);
        }
        #pragma unroll 1
        for (; c < CHUNKS; ++c) {
            const ulonglong2 v = rp[0];
            const ulonglong2 t = sp[0];
            rp += 32;  sp += 32;
            add2(a01, v.x);  add2(a23, v.y);
            fma2(d01, v.x, t.x);  fma2(d23, v.y, t.y);
        }
    }

    // Per-thread totals.
    float aAcc = ((lo2(a01) + hi2(a01)) + (lo2(a23) + hi2(a23))) + am;
    float dAcc = ((lo2(d01) + hi2(d01)) + (lo2(d23) + hi2(d23))) + dm;
    float bAcc = s_sh[i] * dAcc;

    // Warp shuffle reduction (deterministic).
    #pragma unroll
    for (int off = 16; off > 0; off >>= 1) {
        aAcc += __shfl_xor_sync(0xFFFFFFFFu, aAcc, off);
        bAcc += __shfl_xor_sync(0xFFFFFFFFu, bAcc, off);
    }
    if (lane == 0) { sA[wid] = aAcc; sB[wid] = bAcc; }
    __syncthreads();

    if (tid == 0) {
        float a = 0.f, b = 0.f;
        #pragma unroll
        for (int w = 0; w < WARPS_PER_BLOCK; ++w) { a += sA[w]; b += sB[w]; }
        g_partA[blockIdx.x] = a;
        g_partB[blockIdx.x] = b;
        __threadfence();
        const int prev = atomicAdd(&g_count, 1);
        s_isLast = (prev == (int)gridDim.x - 1);
    }
    __syncthreads();

    // Last block performs the final deterministic reduction in double.
    if (s_isLast) {
        __shared__ double rA[THREADS];
        __shared__ double rB[THREADS];
        double a = 0.0, b = 0.0;
        #pragma unroll
        for (int k = tid; k < NBLOCKS; k += THREADS) {
            a += (double)g_partA[k];
            b += (double)g_partB[k];
        }
        rA[tid] = a;
        rB[tid] = b;
        __syncthreads();
        #pragma unroll
        for (int st = THREADS / 2; st > 0; st >>= 1) {
            if (tid < st) { rA[tid] += rA[tid + st]; rB[tid] += rB[tid + st]; }
            __syncthreads();
        }
        if (tid == 0) {
            // out = sum(M)/4 - 0.5 * (sum_{i<j} M_ij s_i s_j + sum_i M_ii s_i)
            out[0] = (float)(rA[0] * 0.25 - 0.5 * rB[0]);
            g_count = 0;   // reset for next graph replay
        }
    }
}

extern "C" void kernel_launch(void* const* d_in, const int* in_sizes, int n_in,
                              void* d_out, int out_size) {
    const float* M = (const float*)d_in[0];   // info_mtx [8192, 8192] fp32
    const float* s = (const float*)d_in[1];   // state [8192] fp32
    float* out = (float*)d_out;

    ising_pass1<<<NBLOCKS, THREADS>>>(M, s, out);
}